// round 10
// baseline (speedup 1.0000x reference)
#include <cuda_runtime.h>
#include <cstdint>

#define HH   128
#define WW   256
#define NN   4
#define CIN  64
#define COUT 128
#define HWSZ (HH * WW)
#define NTAP 9

typedef unsigned long long u64;

// Scratch (static device globals — no runtime allocation)
__device__ float    g_xt[NN * HH * WW * CIN];   // x transposed to [n][y][x][ci]
__device__ uint32_t g_wB[NTAP * 4 * 16 * 32 * 4]; // weights in tf32 B-fragment order
__device__ float2   g_grid[HH * WW * NTAP];     // (ix, iy) unnormalized sample coords
__device__ double   g_nrd[HH * NTAP];
__device__ double   g_dcd[HH * NTAP];

__device__ __forceinline__ uint32_t f2tf32(float v) {
    uint32_t u;
    asm("cvt.rna.tf32.f32 %0, %1;" : "=r"(u) : "f"(v));
    return u;
}

__device__ __forceinline__ void mma_tf32(float* c, uint32_t a0, uint32_t a1,
                                         uint32_t a2, uint32_t a3,
                                         uint32_t b0, uint32_t b1) {
    asm volatile(
        "mma.sync.aligned.m16n8k8.row.col.f32.tf32.tf32.f32 "
        "{%0,%1,%2,%3}, {%4,%5,%6,%7}, {%8,%9}, {%0,%1,%2,%3};"
        : "+f"(c[0]), "+f"(c[1]), "+f"(c[2]), "+f"(c[3])
        : "r"(a0), "r"(a1), "r"(a2), "r"(a3), "r"(b0), "r"(b1));
}

// ---------------------------------------------------------------------------
// Kernel 1a: heavy fp64 trig, only (row, tap)-dependent  (1152 points)
// ---------------------------------------------------------------------------
__global__ void grid1_kernel() {
    int idx = blockIdx.x * blockDim.x + threadIdx.x;
    if (idx >= HH * NTAP) return;
    int r = idx / NTAP, t = idx % NTAP;
    int i = t / 3, j = t % 3;
    const double PI = 3.141592653589793238462643383279502884;
    if (i == 1 && j == 1) {
        g_nrd[idx] = (double)r;
        g_dcd[idx] = 0.0;
        return;
    }
    double dphi = PI / HH, dth = 2.0 * PI / WW;
    double tt = tan(dth), pq = tan(dphi), sp = pq / cos(dth);
    double phi = -(((double)r + 0.5) / HH * PI - PI * 0.5);
    double sphi = sin(phi), cphi = cos(phi);
    double X = (j == 0) ? -tt : (j == 2) ? tt : 0.0;
    double Y;
    if (i == 0)      Y = (j == 1) ?  pq :  sp;
    else if (i == 2) Y = (j == 1) ? -pq : -sp;
    else             Y = 0.0;
    double rho = sqrt(X * X + Y * Y);
    double v   = atan(rho);
    double sv  = sin(v), cv = cos(v);
    double arg = cv * sphi + Y * sv * cphi / rho;
    arg = fmin(1.0, fmax(-1.0, arg));
    double nphi = asin(arg);
    double A    = atan((X * sv) / (rho * cphi * cv - Y * sphi * sv));
    g_nrd[idx] = (-nphi + PI * 0.5) * HH / PI - 0.5;
    g_dcd[idx] = A * WW / (2.0 * PI);
}

// ---------------------------------------------------------------------------
// Kernel 1b: expand to full per-pixel grid (fp64 adds + fp32 cast, exact)
// ---------------------------------------------------------------------------
__global__ void grid2_kernel() {
    int idx = blockIdx.x * blockDim.x + threadIdx.x;
    if (idx >= HWSZ * NTAP) return;
    int p = idx / NTAP, t = idx % NTAP;
    int r = p >> 8, c = p & 255;
    double nr = g_nrd[r * NTAP + t];
    double nc = fmod((double)c + g_dcd[r * NTAP + t] + (double)WW, (double)WW);
    float gx = (float)(nc * 2.0 / WW - 1.0);
    float gy = (float)(nr * 2.0 / HH - 1.0);
    float ix = ((gx + 1.0f) * WW - 1.0f) * 0.5f;
    float iy = ((gy + 1.0f) * HH - 1.0f) * 0.5f;
    g_grid[idx] = make_float2(ix, iy);
}

// ---------------------------------------------------------------------------
// Kernel 2: weights -> tf32 B-fragment layout
//   g_wB[tap][t4][nt][lane][f]: f=0: b0(k8=2t4) f=1: b1(2t4) f=2: b0(2t4+1) f=3: b1(2t4+1)
//   b0: ci = k8*8 + (l&3),  b1: ci = k8*8 + (l&3)+4,  co = nt*8 + (l>>2)
// ---------------------------------------------------------------------------
__global__ void wb_kernel(const float* __restrict__ w) {
    int e = blockIdx.x * blockDim.x + threadIdx.x;
    if (e >= NTAP * 4 * 16 * 32 * 4) return;
    int f  = e & 3;
    int l  = (e >> 2) & 31;
    int nt = (e >> 7) & 15;
    int t4 = (e >> 11) & 3;
    int tap = e >> 13;
    int k8 = t4 * 2 + (f >> 1);
    int ci = k8 * 8 + (l & 3) + ((f & 1) << 2);
    int co = nt * 8 + (l >> 2);
    g_wB[e] = f2tf32(w[(co * CIN + ci) * 9 + tap]);
}

// ---------------------------------------------------------------------------
// Kernel 3: x -> channels-last transpose via shared-memory tiles
// ---------------------------------------------------------------------------
__global__ void xt_kernel(const float* __restrict__ x) {
    __shared__ float tile[CIN][33];
    int b  = blockIdx.x;
    int x0 = (b % (WW / 32)) * 32;
    int ny = b / (WW / 32);
    for (int i = threadIdx.x; i < CIN * 32; i += 256) {
        int ci = i >> 5, xx = i & 31;
        tile[ci][xx] = x[((size_t)(ny / HH * CIN + ci) * HH + (ny % HH)) * WW + x0 + xx];
    }
    __syncthreads();
    for (int i = threadIdx.x; i < CIN * 32; i += 256) {
        int xx = i >> 6, ci = i & 63;
        g_xt[((size_t)ny * WW + x0 + xx) * CIN + ci] = tile[ci][xx];
    }
}

// ---------------------------------------------------------------------------
// Kernel 4: fused bilinear gather + tf32 mma.sync GEMM
//   CTA: 128 px (half row) x 128 co.  8 warps: wm = wid&3 (M 32-strip),
//   wn = wid>>2 (N 64-half).  K = 9 taps x 8 k8-steps.
//   A smem (32KB): [k8 s][mtile][lane-swz] x 16B = frag order (a0,a2,a1,a3)
//   Epilogue smem (64KB, reused): [co][px] pitch 128 floats.
// ---------------------------------------------------------------------------
#define SMEM_TOTAL 65536

__global__ __launch_bounds__(256, 2) void main_kernel(const float* __restrict__ bias,
                                                      float* __restrict__ out) {
    extern __shared__ char smem[];
    const int tid  = threadIdx.x;
    const int wid  = tid >> 5, l = tid & 31;
    const int wm   = wid & 3, wn = wid >> 2;
    const int pix0 = blockIdx.x << 7;
    const int n    = pix0 >> 15;
    const int rc0  = pix0 & (HWSZ - 1);
    const int lswz = l ^ ((l >> 2) & 7);      // per-thread A-smem swizzle

    // gather identity: 1 px per thread, 4 ch-blocks of 8
    const int px  = tid >> 1;
    const int hc  = tid & 1;
    const int mt  = px >> 4;
    const int p7  = px & 7;
    const int hi8 = (px >> 3) & 1;

    const float* __restrict__ xb = g_xt + (size_t)n * (HWSZ * CIN);
    const uint2* __restrict__ wB2 = (const uint2*)g_wB;

    float acc[2][8][4];
    #pragma unroll
    for (int mi = 0; mi < 2; mi++)
        #pragma unroll
        for (int ni = 0; ni < 8; ni++)
            #pragma unroll
            for (int r = 0; r < 4; r++) acc[mi][ni][r] = 0.0f;

    for (int tap = 0; tap < NTAP; tap++) {
        // ---- gather: bilinear sample 64 ch for this px, write A frags -----
        {
            float2 g = g_grid[(rc0 + px) * NTAP + tap];
            float ix = g.x, iy = g.y;
            float fx = floorf(ix), fy = floorf(iy);
            int   x0 = (int)fx, y0 = (int)fy;
            float wx1 = ix - fx, wy1 = iy - fy;
            float wx0 = 1.0f - wx1, wy0 = 1.0f - wy1;
            float mx0 = (x0 >= 0 && x0 < WW)         ? 1.f : 0.f;
            float mx1 = (x0 + 1 >= 0 && x0 + 1 < WW) ? 1.f : 0.f;
            float my0 = (y0 >= 0 && y0 < HH)         ? 1.f : 0.f;
            float my1 = (y0 + 1 >= 0 && y0 + 1 < HH) ? 1.f : 0.f;
            float w00 = wy0 * wx0 * (my0 * mx0);
            float w01 = wy0 * wx1 * (my0 * mx1);
            float w10 = wy1 * wx0 * (my1 * mx0);
            float w11 = wy1 * wx1 * (my1 * mx1);
            int xc0 = min(max(x0, 0), WW - 1);
            int xc1 = min(max(x0 + 1, 0), WW - 1);
            int yc0 = min(max(y0, 0), HH - 1);
            int yc1 = min(max(y0 + 1, 0), HH - 1);
            const float* b00 = xb + (yc0 * WW + xc0) * CIN;
            const float* b01 = xb + (yc0 * WW + xc1) * CIN;
            const float* b10 = xb + (yc1 * WW + xc0) * CIN;
            const float* b11 = xb + (yc1 * WW + xc1) * CIN;
            #pragma unroll
            for (int bi = 0; bi < 4; bi++) {
                int b = hc * 4 + bi;          // k8 slot s = b
                int o = b << 3;               // ci base
                float4 a00 = *(const float4*)(b00 + o);
                float4 a01 = *(const float4*)(b01 + o);
                float4 a10 = *(const float4*)(b10 + o);
                float4 a11 = *(const float4*)(b11 + o);
                float4 c00 = *(const float4*)(b00 + o + 4);
                float4 c01 = *(const float4*)(b01 + o + 4);
                float4 c10 = *(const float4*)(b10 + o + 4);
                float4 c11 = *(const float4*)(b11 + o + 4);
                uint32_t ul[4], uh[4];
                ul[0] = f2tf32(a00.x * w00 + a01.x * w01 + a10.x * w10 + a11.x * w11);
                ul[1] = f2tf32(a00.y * w00 + a01.y * w01 + a10.y * w10 + a11.y * w11);
                ul[2] = f2tf32(a00.z * w00 + a01.z * w01 + a10.z * w10 + a11.z * w11);
                ul[3] = f2tf32(a00.w * w00 + a01.w * w01 + a10.w * w10 + a11.w * w11);
                uh[0] = f2tf32(c00.x * w00 + c01.x * w01 + c10.x * w10 + c11.x * w11);
                uh[1] = f2tf32(c00.y * w00 + c01.y * w01 + c10.y * w10 + c11.y * w11);
                uh[2] = f2tf32(c00.z * w00 + c01.z * w01 + c10.z * w10 + c11.z * w11);
                uh[3] = f2tf32(c00.w * w00 + c01.w * w01 + c10.w * w10 + c11.w * w11);
                uint32_t rowbase = (uint32_t)(((b * 8 + mt) * 32) << 4);
                #pragma unroll
                for (int j = 0; j < 4; j++) {
                    int lsw = (p7 * 4 + j) ^ p7;
                    uint32_t addr = rowbase + (lsw << 4) + (hi8 << 3);
                    asm volatile("{ .reg .b64 t; mov.b64 t, {%1, %2}; st.shared.b64 [%0], t; }"
                        :: "r"((uint32_t)__cvta_generic_to_shared(smem) + addr),
                           "r"(ul[j]), "r"(uh[j]) : "memory");
                }
            }
        }
        __syncthreads();

        // ---- mma phase: 8 k8-steps ---------------------------------------
        #pragma unroll
        for (int s = 0; s < 8; s++) {
            int t4 = s >> 1;
            // A fragments: 2 M-tiles, LDS.128 each (order a0,a2,a1,a3)
            uint32_t a0[2], a1[2], a2[2], a3[2];
            #pragma unroll
            for (int mi = 0; mi < 2; mi++) {
                uint32_t addr = (uint32_t)__cvta_generic_to_shared(smem) +
                                (uint32_t)((((s * 8 + wm * 2 + mi) * 32 + lswz)) << 4);
                asm volatile("ld.shared.v4.b32 {%0,%1,%2,%3}, [%4];"
                    : "=r"(a0[mi]), "=r"(a2[mi]), "=r"(a1[mi]), "=r"(a3[mi]) : "r"(addr));
            }
            // B fragments: 8 N-tiles via LDG.64 (hot in L1/L2)
            uint2 bv[8];
            #pragma unroll
            for (int ni = 0; ni < 8; ni++) {
                int nt = wn * 8 + ni;
                bv[ni] = wB2[(size_t)(((tap * 4 + t4) * 16 + nt) * 32 + l) * 2 + (s & 1)];
            }
            #pragma unroll
            for (int ni = 0; ni < 8; ni++) {
                mma_tf32(acc[0][ni], a0[0], a1[0], a2[0], a3[0], bv[ni].x, bv[ni].y);
                mma_tf32(acc[1][ni], a0[1], a1[1], a2[1], a3[1], bv[ni].x, bv[ni].y);
            }
        }
        __syncthreads();
    }

    // ---- epilogue: accs -> smem [co][px] -> coalesced STG.128 --------------
    float* so = (float*)smem;
    #pragma unroll
    for (int mi = 0; mi < 2; mi++) {
        int pxr = wm * 32 + mi * 16 + (l >> 2);
        #pragma unroll
        for (int ni = 0; ni < 8; ni++) {
            int co = wn * 64 + ni * 8 + (l & 3) * 2;
            so[co * 128 + pxr]           = acc[mi][ni][0];
            so[(co + 1) * 128 + pxr]     = acc[mi][ni][1];
            so[co * 128 + pxr + 8]       = acc[mi][ni][2];
            so[(co + 1) * 128 + pxr + 8] = acc[mi][ni][3];
        }
    }
    __syncthreads();

    float* ob = out + (size_t)n * COUT * HWSZ + rc0 + (l << 2);
    #pragma unroll
    for (int it = 0; it < 16; it++) {
        int co = it * 8 + wid;
        float4 v = *(const float4*)(so + co * 128 + (l << 2));
        float bb = __ldg(&bias[co]);
        v.x += bb; v.y += bb; v.z += bb; v.w += bb;
        *(float4*)(ob + (size_t)co * HWSZ) = v;
    }
}

// ---------------------------------------------------------------------------
extern "C" void kernel_launch(void* const* d_in, const int* in_sizes, int n_in,
                              void* d_out, int out_size) {
    const float* x = (const float*)d_in[0];
    const float* w = (const float*)d_in[1];
    const float* b = (const float*)d_in[2];
    float* out = (float*)d_out;

    cudaFuncSetAttribute(main_kernel,
                         cudaFuncAttributeMaxDynamicSharedMemorySize, SMEM_TOTAL);

    grid1_kernel<<<(HH * NTAP + 127) / 128, 128>>>();
    grid2_kernel<<<(HWSZ * NTAP + 255) / 256, 256>>>();
    wb_kernel<<<(NTAP * 4 * 16 * 32 * 4 + 255) / 256, 256>>>(w);
    xt_kernel<<<NN * HH * (WW / 32), 256>>>(x);
    main_kernel<<<NN * HWSZ / 128, 256, SMEM_TOTAL>>>(b, out);
}

// round 11
// speedup vs baseline: 1.9113x; 1.9113x over previous
#include <cuda_runtime.h>
#include <cstdint>

#define HH   128
#define WW   256
#define NN   4
#define CIN  64
#define COUT 128
#define HWSZ (HH * WW)
#define NTAP 9

// Scratch (static device globals — no runtime allocation)
__device__ float    g_xt[NN * HH * WW * CIN];     // x transposed to [n][y][x][ci]
__device__ uint32_t g_wB[NTAP * 4 * 16 * 32 * 4]; // weights in tf32 B-fragment order
__device__ float2   g_grid[HH * WW * NTAP];       // (ix, iy) unnormalized coords
__device__ double   g_nrd[HH * NTAP];
__device__ double   g_dcd[HH * NTAP];

__device__ __forceinline__ uint32_t f2tf32(float v) {
    uint32_t u;
    asm("cvt.rna.tf32.f32 %0, %1;" : "=r"(u) : "f"(v));
    return u;
}

__device__ __forceinline__ void mma_tf32(float* c, uint32_t a0, uint32_t a1,
                                         uint32_t a2, uint32_t a3,
                                         uint32_t b0, uint32_t b1) {
    asm volatile(
        "mma.sync.aligned.m16n8k8.row.col.f32.tf32.tf32.f32 "
        "{%0,%1,%2,%3}, {%4,%5,%6,%7}, {%8,%9}, {%0,%1,%2,%3};"
        : "+f"(c[0]), "+f"(c[1]), "+f"(c[2]), "+f"(c[3])
        : "r"(a0), "r"(a1), "r"(a2), "r"(a3), "r"(b0), "r"(b1));
}

// ---------------------------------------------------------------------------
// Kernel 1a: heavy fp64 trig, only (row, tap)-dependent  (1152 points)
// ---------------------------------------------------------------------------
__global__ void grid1_kernel() {
    int idx = blockIdx.x * blockDim.x + threadIdx.x;
    if (idx >= HH * NTAP) return;
    int r = idx / NTAP, t = idx % NTAP;
    int i = t / 3, j = t % 3;
    const double PI = 3.141592653589793238462643383279502884;
    if (i == 1 && j == 1) {
        g_nrd[idx] = (double)r;
        g_dcd[idx] = 0.0;
        return;
    }
    double dphi = PI / HH, dth = 2.0 * PI / WW;
    double tt = tan(dth), pq = tan(dphi), sp = pq / cos(dth);
    double phi = -(((double)r + 0.5) / HH * PI - PI * 0.5);
    double sphi = sin(phi), cphi = cos(phi);
    double X = (j == 0) ? -tt : (j == 2) ? tt : 0.0;
    double Y;
    if (i == 0)      Y = (j == 1) ?  pq :  sp;
    else if (i == 2) Y = (j == 1) ? -pq : -sp;
    else             Y = 0.0;
    double rho = sqrt(X * X + Y * Y);
    double v   = atan(rho);
    double sv  = sin(v), cv = cos(v);
    double arg = cv * sphi + Y * sv * cphi / rho;
    arg = fmin(1.0, fmax(-1.0, arg));
    double nphi = asin(arg);
    double A    = atan((X * sv) / (rho * cphi * cv - Y * sphi * sv));
    g_nrd[idx] = (-nphi + PI * 0.5) * HH / PI - 0.5;
    g_dcd[idx] = A * WW / (2.0 * PI);
}

// ---------------------------------------------------------------------------
// Kernel 1b: expand to full per-pixel grid (fp64 adds + fp32 cast, exact)
// ---------------------------------------------------------------------------
__global__ void grid2_kernel() {
    int idx = blockIdx.x * blockDim.x + threadIdx.x;
    if (idx >= HWSZ * NTAP) return;
    int p = idx / NTAP, t = idx % NTAP;
    int r = p >> 8, c = p & 255;
    double nr = g_nrd[r * NTAP + t];
    double nc = fmod((double)c + g_dcd[r * NTAP + t] + (double)WW, (double)WW);
    float gx = (float)(nc * 2.0 / WW - 1.0);
    float gy = (float)(nr * 2.0 / HH - 1.0);
    float ix = ((gx + 1.0f) * WW - 1.0f) * 0.5f;
    float iy = ((gy + 1.0f) * HH - 1.0f) * 0.5f;
    g_grid[idx] = make_float2(ix, iy);
}

// ---------------------------------------------------------------------------
// Kernel 2: weights -> tf32 B-fragment layout
// ---------------------------------------------------------------------------
__global__ void wb_kernel(const float* __restrict__ w) {
    int e = blockIdx.x * blockDim.x + threadIdx.x;
    if (e >= NTAP * 4 * 16 * 32 * 4) return;
    int f  = e & 3;
    int l  = (e >> 2) & 31;
    int nt = (e >> 7) & 15;
    int t4 = (e >> 11) & 3;
    int tap = e >> 13;
    int k8 = t4 * 2 + (f >> 1);
    int ci = k8 * 8 + (l & 3) + ((f & 1) << 2);
    int co = nt * 8 + (l >> 2);
    g_wB[e] = f2tf32(w[(co * CIN + ci) * 9 + tap]);
}

// ---------------------------------------------------------------------------
// Kernel 3: x -> channels-last transpose via shared-memory tiles
// ---------------------------------------------------------------------------
__global__ void xt_kernel(const float* __restrict__ x) {
    __shared__ float tile[CIN][33];
    int b  = blockIdx.x;
    int x0 = (b % (WW / 32)) * 32;
    int ny = b / (WW / 32);
    for (int i = threadIdx.x; i < CIN * 32; i += 256) {
        int ci = i >> 5, xx = i & 31;
        tile[ci][xx] = x[((size_t)(ny / HH * CIN + ci) * HH + (ny % HH)) * WW + x0 + xx];
    }
    __syncthreads();
    for (int i = threadIdx.x; i < CIN * 32; i += 256) {
        int xx = i >> 6, ci = i & 63;
        g_xt[((size_t)ny * WW + x0 + xx) * CIN + ci] = tile[ci][xx];
    }
}

// ---------------------------------------------------------------------------
// Kernel 4: fused separable gather + tf32 mma.sync GEMM
//   Per (CTA row, tap): iy is constant; ix = ix0 + p exactly.  So:
//     stage:   coalesced load 2 contiguous row segments (132 cols x 64 ch),
//              vertical blend in registers, STS to staging (pitch 272B).
//     combine: per-px horizontal 2-tap blend from staging -> tf32 A frags.
//     mma:     8 k8-steps, identical to R10.
//   smem: [0, 35904)      staging (132 cols x 68 floats)
//         [36864, 69632)  A-frag buffer (32KB); epilogue reuses [0, 64KB)
// ---------------------------------------------------------------------------
#define NCOLS   132
#define SPITCHB 272              // staging pitch bytes (68 floats)
#define SMEM_AF 36864
#define SMEM_TOTAL 69632

__global__ __launch_bounds__(256, 2) void main_kernel(const float* __restrict__ bias,
                                                      float* __restrict__ out) {
    extern __shared__ char smem[];
    float* sstage = (float*)smem;
    const uint32_t smem_u = (uint32_t)__cvta_generic_to_shared(smem);
    const int tid  = threadIdx.x;
    const int wid  = tid >> 5, l = tid & 31;
    const int wm   = wid & 3, wn = wid >> 2;
    const int pix0 = blockIdx.x << 7;
    const int n    = pix0 >> 15;
    const int rc0  = pix0 & (HWSZ - 1);
    const int lswz = l ^ ((l >> 2) & 7);

    // combine identity: px = tid&127 (lane-contiguous), hc = tid>>7
    const int px  = tid & 127;
    const int hc  = tid >> 7;
    const int mt  = px >> 4;
    const int p7  = px & 7;
    const int hi8 = (px >> 3) & 1;

    const float* __restrict__ xb = g_xt + (size_t)n * (HWSZ * CIN);
    const uint2* __restrict__ wB2 = (const uint2*)g_wB;

    float acc[2][8][4];
    #pragma unroll
    for (int mi = 0; mi < 2; mi++)
        #pragma unroll
        for (int ni = 0; ni < 8; ni++)
            #pragma unroll
            for (int r = 0; r < 4; r++) acc[mi][ni][r] = 0.0f;

    for (int tap = 0; tap < NTAP; tap++) {
        // ---- per-tap row constants (identical for all px in this CTA) ----
        float2 g0 = g_grid[rc0 * NTAP + tap];
        float iy = g0.y;
        float fy = floorf(iy);
        int   y0 = (int)fy;
        float wy1 = iy - fy, wy0 = 1.0f - wy1;
        float W0 = (y0 >= 0     && y0 < HH)     ? wy0 : 0.0f;
        float W1 = (y0 + 1 >= 0 && y0 + 1 < HH) ? wy1 : 0.0f;
        int yc0 = min(max(y0, 0), HH - 1);
        int yc1 = min(max(y0 + 1, 0), HH - 1);
        int xstart = (int)floorf(g0.x) - 2;
        const float* __restrict__ r0 = xb + (size_t)yc0 * (WW * CIN);
        const float* __restrict__ r1 = xb + (size_t)yc1 * (WW * CIN);

        // ---- stage: 132 cols x 16 chunks of 16B, coalesced + v-blend ------
        #pragma unroll
        for (int it = 0; it < 9; it++) {
            int e = tid + (it << 8);
            if (e < NCOLS * 16) {
                int col = e >> 4, ck = e & 15;
                int cidx = (xstart + col) & 255;
                int off = cidx * CIN + (ck << 2);
                float4 a = *(const float4*)(r0 + off);
                float4 b = *(const float4*)(r1 + off);
                float4 v;
                v.x = a.x * W0 + b.x * W1;
                v.y = a.y * W0 + b.y * W1;
                v.z = a.z * W0 + b.z * W1;
                v.w = a.w * W0 + b.w * W1;
                *(float4*)((char*)sstage + col * SPITCHB + (ck << 4)) = v;
            }
        }
        __syncthreads();

        // ---- combine: horizontal 2-tap blend -> tf32 A fragments ----------
        {
            float2 g = g_grid[(rc0 + px) * NTAP + tap];
            float ix = g.x;
            float fx = floorf(ix);
            int   x0 = (int)fx;
            float wx1 = ix - fx, wx0 = 1.0f - wx1;
            float U0 = (x0 >= 0) ? wx0 : 0.0f;            // x0 in [-1, 255]
            float U1 = (x0 + 1 <= WW - 1) ? wx1 : 0.0f;
            int xc0 = max(x0, 0);
            int xc1 = min(x0 + 1, WW - 1);
            const float* p0 = (const float*)((char*)sstage + (((xc0 - xstart) & 255) * SPITCHB));
            const float* p1 = (const float*)((char*)sstage + (((xc1 - xstart) & 255) * SPITCHB));
            #pragma unroll
            for (int bi = 0; bi < 4; bi++) {
                int b = hc * 4 + bi;
                int o = b << 3;
                float4 A0 = *(const float4*)(p0 + o);
                float4 A1 = *(const float4*)(p1 + o);
                float4 C0 = *(const float4*)(p0 + o + 4);
                float4 C1 = *(const float4*)(p1 + o + 4);
                uint32_t ul[4], uh[4];
                ul[0] = f2tf32(A0.x * U0 + A1.x * U1);
                ul[1] = f2tf32(A0.y * U0 + A1.y * U1);
                ul[2] = f2tf32(A0.z * U0 + A1.z * U1);
                ul[3] = f2tf32(A0.w * U0 + A1.w * U1);
                uh[0] = f2tf32(C0.x * U0 + C1.x * U1);
                uh[1] = f2tf32(C0.y * U0 + C1.y * U1);
                uh[2] = f2tf32(C0.z * U0 + C1.z * U1);
                uh[3] = f2tf32(C0.w * U0 + C1.w * U1);
                uint32_t rowbase = (uint32_t)(((b * 8 + mt) * 32) << 4);
                #pragma unroll
                for (int j = 0; j < 4; j++) {
                    int lsw = (p7 * 4 + j) ^ p7;
                    uint32_t addr = smem_u + SMEM_AF + rowbase + (lsw << 4) + (hi8 << 3);
                    asm volatile("{ .reg .b64 t; mov.b64 t, {%1, %2}; st.shared.b64 [%0], t; }"
                        :: "r"(addr), "r"(ul[j]), "r"(uh[j]) : "memory");
                }
            }
        }
        __syncthreads();

        // ---- mma phase: 8 k8-steps ----------------------------------------
        #pragma unroll
        for (int s = 0; s < 8; s++) {
            int t4 = s >> 1;
            uint32_t a0[2], a1[2], a2[2], a3[2];
            #pragma unroll
            for (int mi = 0; mi < 2; mi++) {
                uint32_t addr = smem_u + SMEM_AF +
                                (uint32_t)((((s * 8 + wm * 2 + mi) * 32 + lswz)) << 4);
                asm volatile("ld.shared.v4.b32 {%0,%1,%2,%3}, [%4];"
                    : "=r"(a0[mi]), "=r"(a2[mi]), "=r"(a1[mi]), "=r"(a3[mi]) : "r"(addr));
            }
            uint2 bv[8];
            #pragma unroll
            for (int ni = 0; ni < 8; ni++) {
                int nt = wn * 8 + ni;
                bv[ni] = wB2[(size_t)(((tap * 4 + t4) * 16 + nt) * 32 + l) * 2 + (s & 1)];
            }
            #pragma unroll
            for (int ni = 0; ni < 8; ni++) {
                mma_tf32(acc[0][ni], a0[0], a1[0], a2[0], a3[0], bv[ni].x, bv[ni].y);
                mma_tf32(acc[1][ni], a0[1], a1[1], a2[1], a3[1], bv[ni].x, bv[ni].y);
            }
        }
        // no sync needed here: next stage writes staging, mma read A-frags;
        // the post-stage __syncthreads orders everything.
    }
    __syncthreads();

    // ---- epilogue: accs -> smem [co][px] -> coalesced STG.128 --------------
    float* so = (float*)smem;
    #pragma unroll
    for (int mi = 0; mi < 2; mi++) {
        int pxr = wm * 32 + mi * 16 + (l >> 2);
        #pragma unroll
        for (int ni = 0; ni < 8; ni++) {
            int co = wn * 64 + ni * 8 + (l & 3) * 2;
            so[co * 128 + pxr]           = acc[mi][ni][0];
            so[(co + 1) * 128 + pxr]     = acc[mi][ni][1];
            so[co * 128 + pxr + 8]       = acc[mi][ni][2];
            so[(co + 1) * 128 + pxr + 8] = acc[mi][ni][3];
        }
    }
    __syncthreads();

    float* ob = out + (size_t)n * COUT * HWSZ + rc0 + (l << 2);
    #pragma unroll
    for (int it = 0; it < 16; it++) {
        int co = it * 8 + wid;
        float4 v = *(const float4*)(so + co * 128 + (l << 2));
        float bb = __ldg(&bias[co]);
        v.x += bb; v.y += bb; v.z += bb; v.w += bb;
        *(float4*)(ob + (size_t)co * HWSZ) = v;
    }
}

// ---------------------------------------------------------------------------
extern "C" void kernel_launch(void* const* d_in, const int* in_sizes, int n_in,
                              void* d_out, int out_size) {
    const float* x = (const float*)d_in[0];
    const float* w = (const float*)d_in[1];
    const float* b = (const float*)d_in[2];
    float* out = (float*)d_out;

    cudaFuncSetAttribute(main_kernel,
                         cudaFuncAttributeMaxDynamicSharedMemorySize, SMEM_TOTAL);

    grid1_kernel<<<(HH * NTAP + 127) / 128, 128>>>();
    grid2_kernel<<<(HWSZ * NTAP + 255) / 256, 256>>>();
    wb_kernel<<<(NTAP * 4 * 16 * 32 * 4 + 255) / 256, 256>>>(w);
    xt_kernel<<<NN * HH * (WW / 32), 256>>>(x);
    main_kernel<<<NN * HWSZ / 128, 256, SMEM_TOTAL>>>(b, out);
}

// round 13
// speedup vs baseline: 2.3173x; 1.2125x over previous
#include <cuda_runtime.h>
#include <cstdint>

#define HH   128
#define WW   256
#define NN   4
#define CIN  64
#define COUT 128
#define HWSZ (HH * WW)
#define NTAP 9

// Scratch (static device globals — no runtime allocation)
__device__ float    g_xt[NN * HH * WW * CIN];     // x transposed to [n][y][x][ci]
__device__ uint2    g_wB[NTAP * 4 * 16 * 32];     // weights in f16 B-fragment order
__device__ float2   g_grid[HH * WW * NTAP];       // (ix, iy) unnormalized coords
__device__ double   g_nrd[HH * NTAP];
__device__ double   g_dcd[HH * NTAP];

__device__ __forceinline__ uint32_t pack_f16x2(float lo, float hi) {
    uint32_t d;  // cvt.rn.f16x2.f32 d, a, b  ->  d.hi = a, d.lo = b
    asm("cvt.rn.f16x2.f32 %0, %1, %2;" : "=r"(d) : "f"(hi), "f"(lo));
    return d;
}

__device__ __forceinline__ void mma_f16(float* c, uint32_t a0, uint32_t a1,
                                        uint32_t a2, uint32_t a3,
                                        uint32_t b0, uint32_t b1) {
    asm volatile(
        "mma.sync.aligned.m16n8k16.row.col.f32.f16.f16.f32 "
        "{%0,%1,%2,%3}, {%4,%5,%6,%7}, {%8,%9}, {%0,%1,%2,%3};"
        : "+f"(c[0]), "+f"(c[1]), "+f"(c[2]), "+f"(c[3])
        : "r"(a0), "r"(a1), "r"(a2), "r"(a3), "r"(b0), "r"(b1));
}

// ---------------------------------------------------------------------------
// Kernel 1a: heavy fp64 trig, only (row, tap)-dependent  (1152 points)
// ---------------------------------------------------------------------------
__global__ void grid1_kernel() {
    int idx = blockIdx.x * blockDim.x + threadIdx.x;
    if (idx >= HH * NTAP) return;
    int r = idx / NTAP, t = idx % NTAP;
    int i = t / 3, j = t % 3;
    const double PI = 3.141592653589793238462643383279502884;
    if (i == 1 && j == 1) {
        g_nrd[idx] = (double)r;
        g_dcd[idx] = 0.0;
        return;
    }
    double dphi = PI / HH, dth = 2.0 * PI / WW;
    double tt = tan(dth), pq = tan(dphi), sp = pq / cos(dth);
    double phi = -(((double)r + 0.5) / HH * PI - PI * 0.5);
    double sphi = sin(phi), cphi = cos(phi);
    double X = (j == 0) ? -tt : (j == 2) ? tt : 0.0;
    double Y;
    if (i == 0)      Y = (j == 1) ?  pq :  sp;
    else if (i == 2) Y = (j == 1) ? -pq : -sp;
    else             Y = 0.0;
    double rho = sqrt(X * X + Y * Y);
    double v   = atan(rho);
    double sv  = sin(v), cv = cos(v);
    double arg = cv * sphi + Y * sv * cphi / rho;
    arg = fmin(1.0, fmax(-1.0, arg));
    double nphi = asin(arg);
    double A    = atan((X * sv) / (rho * cphi * cv - Y * sphi * sv));
    g_nrd[idx] = (-nphi + PI * 0.5) * HH / PI - 0.5;
    g_dcd[idx] = A * WW / (2.0 * PI);
}

// ---------------------------------------------------------------------------
// Kernel 1b: expand to full per-pixel grid (fp64 adds + fp32 cast, exact)
// ---------------------------------------------------------------------------
__global__ void grid2_kernel() {
    int idx = blockIdx.x * blockDim.x + threadIdx.x;
    if (idx >= HWSZ * NTAP) return;
    int p = idx / NTAP, t = idx % NTAP;
    int r = p >> 8, c = p & 255;
    double nr = g_nrd[r * NTAP + t];
    double nc = fmod((double)c + g_dcd[r * NTAP + t] + (double)WW, (double)WW);
    float gx = (float)(nc * 2.0 / WW - 1.0);
    float gy = (float)(nr * 2.0 / HH - 1.0);
    float ix = ((gx + 1.0f) * WW - 1.0f) * 0.5f;
    float iy = ((gy + 1.0f) * HH - 1.0f) * 0.5f;
    g_grid[idx] = make_float2(ix, iy);
}

// ---------------------------------------------------------------------------
// Kernel 2: weights -> f16 B-fragment layout (m16n8k16)
//   entry [tap][s][nt][l]: b0 = {ci=s*16+2(l&3), +1}, b1 = {+8, +9}, co=nt*8+(l>>2)
// ---------------------------------------------------------------------------
__global__ void wb_kernel(const float* __restrict__ w) {
    int e = blockIdx.x * blockDim.x + threadIdx.x;
    if (e >= NTAP * 4 * 16 * 32) return;
    int l   = e & 31;
    int nt  = (e >> 5) & 15;
    int s   = (e >> 9) & 3;
    int tap = e >> 11;
    int co  = nt * 8 + (l >> 2);
    int k0  = s * 16 + 2 * (l & 3);
    float w0 = w[(co * CIN + k0) * 9 + tap];
    float w1 = w[(co * CIN + k0 + 1) * 9 + tap];
    float w2 = w[(co * CIN + k0 + 8) * 9 + tap];
    float w3 = w[(co * CIN + k0 + 9) * 9 + tap];
    uint2 v;
    v.x = pack_f16x2(w0, w1);
    v.y = pack_f16x2(w2, w3);
    g_wB[e] = v;
}

// ---------------------------------------------------------------------------
// Kernel 3: x -> channels-last transpose via shared-memory tiles
// ---------------------------------------------------------------------------
__global__ void xt_kernel(const float* __restrict__ x) {
    __shared__ float tile[CIN][33];
    int b  = blockIdx.x;
    int x0 = (b % (WW / 32)) * 32;
    int ny = b / (WW / 32);
    for (int i = threadIdx.x; i < CIN * 32; i += 256) {
        int ci = i >> 5, xx = i & 31;
        tile[ci][xx] = x[((size_t)(ny / HH * CIN + ci) * HH + (ny % HH)) * WW + x0 + xx];
    }
    __syncthreads();
    for (int i = threadIdx.x; i < CIN * 32; i += 256) {
        int xx = i >> 6, ci = i & 63;
        g_xt[((size_t)ny * WW + x0 + xx) * CIN + ci] = tile[ci][xx];
    }
}

// ---------------------------------------------------------------------------
// Kernel 4: fused separable gather + f16 mma.sync GEMM
//   stage:   coalesced 2-row load + vertical blend (fp32) -> staging smem
//   combine: horizontal 2-tap blend (fp32) -> f16x2 A-fragments (m16n8k16)
//   mma:     4 k16-steps per tap
//   smem: [0, 35904)      staging (132 cols x 68 floats)
//         [36864, 53248)  A-frag buffer (16KB, f16)
//         epilogue reuses [0, 64KB)
// ---------------------------------------------------------------------------
#define NCOLS   132
#define SPITCHB 272              // staging pitch bytes (68 floats)
#define SMEM_AF 36864
#define SMEM_TOTAL 69632

__global__ __launch_bounds__(256, 2) void main_kernel(const float* __restrict__ bias,
                                                      float* __restrict__ out) {
    extern __shared__ char smem[];
    float* sstage = (float*)smem;
    const uint32_t smem_u = (uint32_t)__cvta_generic_to_shared(smem);
    const int tid  = threadIdx.x;
    const int wid  = tid >> 5, l = tid & 31;
    const int wm   = wid & 3, wn = wid >> 2;
    const int pix0 = blockIdx.x << 7;
    const int n    = pix0 >> 15;
    const int rc0  = pix0 & (HWSZ - 1);
    const int lswz = l ^ ((l >> 2) & 7);

    // combine identity: px = tid&127 (lane-contiguous), hc = tid>>7
    const int px  = tid & 127;
    const int hc  = tid >> 7;
    const int mt  = px >> 4;
    const int p7  = px & 7;
    const int hi8 = (px >> 3) & 1;

    const float* __restrict__ xb = g_xt + (size_t)n * (HWSZ * CIN);

    float acc[2][8][4];
    #pragma unroll
    for (int mi = 0; mi < 2; mi++)
        #pragma unroll
        for (int ni = 0; ni < 8; ni++)
            #pragma unroll
            for (int r = 0; r < 4; r++) acc[mi][ni][r] = 0.0f;

    for (int tap = 0; tap < NTAP; tap++) {
        // ---- per-tap row constants ---------------------------------------
        float2 g0 = g_grid[rc0 * NTAP + tap];
        float iy = g0.y;
        float fy = floorf(iy);
        int   y0 = (int)fy;
        float wy1 = iy - fy, wy0 = 1.0f - wy1;
        float W0 = (y0 >= 0     && y0 < HH)     ? wy0 : 0.0f;
        float W1 = (y0 + 1 >= 0 && y0 + 1 < HH) ? wy1 : 0.0f;
        int yc0 = min(max(y0, 0), HH - 1);
        int yc1 = min(max(y0 + 1, 0), HH - 1);
        int xstart = (int)floorf(g0.x) - 2;
        const float* __restrict__ r0 = xb + (size_t)yc0 * (WW * CIN);
        const float* __restrict__ r1 = xb + (size_t)yc1 * (WW * CIN);

        // ---- stage: 132 cols x 16 chunks of 16B, coalesced + v-blend ------
        #pragma unroll
        for (int it = 0; it < 9; it++) {
            int e = tid + (it << 8);
            if (e < NCOLS * 16) {
                int col = e >> 4, ck = e & 15;
                int cidx = (xstart + col) & 255;
                int off = cidx * CIN + (ck << 2);
                float4 a = *(const float4*)(r0 + off);
                float4 b = *(const float4*)(r1 + off);
                float4 v;
                v.x = a.x * W0 + b.x * W1;
                v.y = a.y * W0 + b.y * W1;
                v.z = a.z * W0 + b.z * W1;
                v.w = a.w * W0 + b.w * W1;
                *(float4*)((char*)sstage + col * SPITCHB + (ck << 4)) = v;
            }
        }
        __syncthreads();

        // ---- combine: horizontal 2-tap blend -> f16 A fragments -----------
        {
            float2 g = g_grid[(rc0 + px) * NTAP + tap];
            float ix = g.x;
            float fx = floorf(ix);
            int   x0 = (int)fx;
            float wx1 = ix - fx, wx0 = 1.0f - wx1;
            float U0 = (x0 >= 0) ? wx0 : 0.0f;            // x0 in [-1, 255]
            float U1 = (x0 + 1 <= WW - 1) ? wx1 : 0.0f;
            int xc0 = max(x0, 0);
            int xc1 = min(x0 + 1, WW - 1);
            const float* p0 = (const float*)((char*)sstage + (((xc0 - xstart) & 255) * SPITCHB));
            const float* p1 = (const float*)((char*)sstage + (((xc1 - xstart) & 255) * SPITCHB));
            #pragma unroll
            for (int si = 0; si < 2; si++) {
                int s = (hc << 1) + si;
                int o = s << 4;               // ch base: 16 ch per k16-step
                float v[16];
                #pragma unroll
                for (int q = 0; q < 4; q++) {
                    float4 A0 = *(const float4*)(p0 + o + (q << 2));
                    float4 A1 = *(const float4*)(p1 + o + (q << 2));
                    v[q * 4 + 0] = A0.x * U0 + A1.x * U1;
                    v[q * 4 + 1] = A0.y * U0 + A1.y * U1;
                    v[q * 4 + 2] = A0.z * U0 + A1.z * U1;
                    v[q * 4 + 3] = A0.w * U0 + A1.w * U1;
                }
                #pragma unroll
                for (int j = 0; j < 4; j++) {
                    uint32_t lo = pack_f16x2(v[2 * j],     v[2 * j + 1]);
                    uint32_t hi = pack_f16x2(v[2 * j + 8], v[2 * j + 9]);
                    // memory reg order per 16B unit: a0(@0) a2(@4) a1(@8) a3(@12)
                    int lsw = (p7 * 4 + j) ^ p7;
                    uint32_t addr = smem_u + SMEM_AF +
                                    (uint32_t)((((s * 8 + mt) * 32 + lsw) << 4) + (hi8 << 3));
                    asm volatile("st.shared.v2.b32 [%0], {%1, %2};"
                        :: "r"(addr), "r"(lo), "r"(hi) : "memory");
                }
            }
        }
        __syncthreads();

        // ---- mma phase: 4 k16-steps ---------------------------------------
        #pragma unroll
        for (int s = 0; s < 4; s++) {
            uint32_t a0[2], a1[2], a2[2], a3[2];
            #pragma unroll
            for (int mi = 0; mi < 2; mi++) {
                uint32_t addr = smem_u + SMEM_AF +
                                (uint32_t)((((s * 8 + wm * 2 + mi) * 32 + lswz)) << 4);
                asm volatile("ld.shared.v4.b32 {%0,%1,%2,%3}, [%4];"
                    : "=r"(a0[mi]), "=r"(a2[mi]), "=r"(a1[mi]), "=r"(a3[mi]) : "r"(addr));
            }
            uint2 bv[8];
            #pragma unroll
            for (int ni = 0; ni < 8; ni++) {
                int nt = wn * 8 + ni;
                bv[ni] = g_wB[((tap * 4 + s) * 16 + nt) * 32 + l];
            }
            #pragma unroll
            for (int ni = 0; ni < 8; ni++) {
                mma_f16(acc[0][ni], a0[0], a1[0], a2[0], a3[0], bv[ni].x, bv[ni].y);
                mma_f16(acc[1][ni], a0[1], a1[1], a2[1], a3[1], bv[ni].x, bv[ni].y);
            }
        }
        // no sync needed: next stage writes staging, mma reads A-frags;
        // the post-stage __syncthreads orders everything.
    }
    __syncthreads();

    // ---- epilogue: accs -> smem [co][px] -> coalesced STG.128 --------------
    float* so = (float*)smem;
    #pragma unroll
    for (int mi = 0; mi < 2; mi++) {
        int pxr = wm * 32 + mi * 16 + (l >> 2);
        #pragma unroll
        for (int ni = 0; ni < 8; ni++) {
            int co = wn * 64 + ni * 8 + (l & 3) * 2;
            so[co * 128 + pxr]           = acc[mi][ni][0];
            so[(co + 1) * 128 + pxr]     = acc[mi][ni][1];
            so[co * 128 + pxr + 8]       = acc[mi][ni][2];
            so[(co + 1) * 128 + pxr + 8] = acc[mi][ni][3];
        }
    }
    __syncthreads();

    float* ob = out + (size_t)n * COUT * HWSZ + rc0 + (l << 2);
    #pragma unroll
    for (int it = 0; it < 16; it++) {
        int co = it * 8 + wid;
        float4 v = *(const float4*)(so + co * 128 + (l << 2));
        float bb = __ldg(&bias[co]);
        v.x += bb; v.y += bb; v.z += bb; v.w += bb;
        *(float4*)(ob + (size_t)co * HWSZ) = v;
    }
}

// ---------------------------------------------------------------------------
extern "C" void kernel_launch(void* const* d_in, const int* in_sizes, int n_in,
                              void* d_out, int out_size) {
    const float* x = (const float*)d_in[0];
    const float* w = (const float*)d_in[1];
    const float* b = (const float*)d_in[2];
    float* out = (float*)d_out;

    cudaFuncSetAttribute(main_kernel,
                         cudaFuncAttributeMaxDynamicSharedMemorySize, SMEM_TOTAL);

    grid1_kernel<<<(HH * NTAP + 127) / 128, 128>>>();
    grid2_kernel<<<(HWSZ * NTAP + 255) / 256, 256>>>();
    wb_kernel<<<(NTAP * 4 * 16 * 32 + 255) / 256, 256>>>(w);
    xt_kernel<<<NN * HH * (WW / 32), 256>>>(x);
    main_kernel<<<NN * HWSZ / 128, 256, SMEM_TOTAL>>>(b, out);
}

// round 15
// speedup vs baseline: 2.7609x; 1.1914x over previous
#include <cuda_runtime.h>
#include <cstdint>

#define HH   128
#define WW   256
#define NN   4
#define CIN  64
#define COUT 128
#define HWSZ (HH * WW)
#define NTAP 9

// Scratch (static device globals — no runtime allocation)
__device__ float    g_xt[NN * HH * WW * CIN];     // x transposed to [n][y][x][ci]
__device__ uint2    g_wB[NTAP * 4 * 16 * 32];     // weights in f16 B-fragment order
__device__ float2   g_grid[HH * WW * NTAP];       // (ix, iy) unnormalized coords
__device__ double   g_nrd[HH * NTAP];
__device__ double   g_dcd[HH * NTAP];

__device__ __forceinline__ uint32_t pack_f16x2(float lo, float hi) {
    uint32_t d;  // cvt.rn.f16x2.f32 d, a, b  ->  d.hi = a, d.lo = b
    asm("cvt.rn.f16x2.f32 %0, %1, %2;" : "=r"(d) : "f"(hi), "f"(lo));
    return d;
}
#define HMUL2(d, a, b)     asm("mul.f16x2 %0, %1, %2;" : "=r"(d) : "r"(a), "r"(b))
#define HFMA2(d, a, b, c)  asm("fma.rn.f16x2 %0, %1, %2, %3;" : "=r"(d) : "r"(a), "r"(b), "r"(c))

__device__ __forceinline__ void mma_f16(float* c, uint32_t a0, uint32_t a1,
                                        uint32_t a2, uint32_t a3,
                                        uint32_t b0, uint32_t b1) {
    asm volatile(
        "mma.sync.aligned.m16n8k16.row.col.f32.f16.f16.f32 "
        "{%0,%1,%2,%3}, {%4,%5,%6,%7}, {%8,%9}, {%0,%1,%2,%3};"
        : "+f"(c[0]), "+f"(c[1]), "+f"(c[2]), "+f"(c[3])
        : "r"(a0), "r"(a1), "r"(a2), "r"(a3), "r"(b0), "r"(b1));
}

// ---------------------------------------------------------------------------
// Kernel 1a: heavy fp64 trig, only (row, tap)-dependent  (1152 points)
// ---------------------------------------------------------------------------
__global__ void grid1_kernel() {
    int idx = blockIdx.x * blockDim.x + threadIdx.x;
    if (idx >= HH * NTAP) return;
    int r = idx / NTAP, t = idx % NTAP;
    int i = t / 3, j = t % 3;
    const double PI = 3.141592653589793238462643383279502884;
    if (i == 1 && j == 1) {
        g_nrd[idx] = (double)r;
        g_dcd[idx] = 0.0;
        return;
    }
    double dphi = PI / HH, dth = 2.0 * PI / WW;
    double tt = tan(dth), pq = tan(dphi), sp = pq / cos(dth);
    double phi = -(((double)r + 0.5) / HH * PI - PI * 0.5);
    double sphi = sin(phi), cphi = cos(phi);
    double X = (j == 0) ? -tt : (j == 2) ? tt : 0.0;
    double Y;
    if (i == 0)      Y = (j == 1) ?  pq :  sp;
    else if (i == 2) Y = (j == 1) ? -pq : -sp;
    else             Y = 0.0;
    double rho = sqrt(X * X + Y * Y);
    double v   = atan(rho);
    double sv  = sin(v), cv = cos(v);
    double arg = cv * sphi + Y * sv * cphi / rho;
    arg = fmin(1.0, fmax(-1.0, arg));
    double nphi = asin(arg);
    double A    = atan((X * sv) / (rho * cphi * cv - Y * sphi * sv));
    g_nrd[idx] = (-nphi + PI * 0.5) * HH / PI - 0.5;
    g_dcd[idx] = A * WW / (2.0 * PI);
}

// ---------------------------------------------------------------------------
// Kernel 1b: expand to full per-pixel grid (fp64 adds + fp32 cast, exact)
// ---------------------------------------------------------------------------
__global__ void grid2_kernel() {
    int idx = blockIdx.x * blockDim.x + threadIdx.x;
    if (idx >= HWSZ * NTAP) return;
    int p = idx / NTAP, t = idx % NTAP;
    int r = p >> 8, c = p & 255;
    double nr = g_nrd[r * NTAP + t];
    double t2 = (double)c + g_dcd[r * NTAP + t];
    double nc = (t2 >= 0.0) ? ((t2 < 256.0) ? t2 : t2 - 256.0) : t2 + 256.0;
    float gx = (float)(nc * 2.0 / WW - 1.0);
    float gy = (float)(nr * 2.0 / HH - 1.0);
    float ix = ((gx + 1.0f) * WW - 1.0f) * 0.5f;
    float iy = ((gy + 1.0f) * HH - 1.0f) * 0.5f;
    g_grid[idx] = make_float2(ix, iy);
}

// ---------------------------------------------------------------------------
// Kernel 2: weights -> f16 B-fragment layout (m16n8k16)
// ---------------------------------------------------------------------------
__global__ void wb_kernel(const float* __restrict__ w) {
    int e = blockIdx.x * blockDim.x + threadIdx.x;
    if (e >= NTAP * 4 * 16 * 32) return;
    int l   = e & 31;
    int nt  = (e >> 5) & 15;
    int s   = (e >> 9) & 3;
    int tap = e >> 11;
    int co  = nt * 8 + (l >> 2);
    int k0  = s * 16 + 2 * (l & 3);
    float w0 = w[(co * CIN + k0) * 9 + tap];
    float w1 = w[(co * CIN + k0 + 1) * 9 + tap];
    float w2 = w[(co * CIN + k0 + 8) * 9 + tap];
    float w3 = w[(co * CIN + k0 + 9) * 9 + tap];
    uint2 v;
    v.x = pack_f16x2(w0, w1);
    v.y = pack_f16x2(w2, w3);
    g_wB[e] = v;
}

// ---------------------------------------------------------------------------
// Kernel 3: x -> channels-last transpose, float4 both directions
// ---------------------------------------------------------------------------
__global__ void xt_kernel(const float* __restrict__ x) {
    __shared__ float tile[CIN][33];
    int b  = blockIdx.x;
    int x0 = (b & 7) * 32;            // WW/32 = 8
    int ny = b >> 3;                  // n*HH + y
    int n  = ny / HH, y = ny % HH;
    const float* xb = x + (size_t)n * CIN * HWSZ + (size_t)y * WW + x0;
    #pragma unroll
    for (int it = 0; it < 2; it++) {
        int i = threadIdx.x + it * 256;     // 512 tasks: ci x f4
        int ci = i >> 3, f4 = i & 7;
        float4 v = *(const float4*)(xb + (size_t)ci * HWSZ + (f4 << 2));
        tile[ci][(f4 << 2) + 0] = v.x;
        tile[ci][(f4 << 2) + 1] = v.y;
        tile[ci][(f4 << 2) + 2] = v.z;
        tile[ci][(f4 << 2) + 3] = v.w;
    }
    __syncthreads();
    float* ob = g_xt + ((size_t)ny * WW + x0) * CIN;
    #pragma unroll
    for (int it = 0; it < 2; it++) {
        int i = threadIdx.x + it * 256;     // 512 tasks: xx x c4
        int xx = i >> 4, c4 = i & 15;
        float4 v;
        v.x = tile[(c4 << 2) + 0][xx];
        v.y = tile[(c4 << 2) + 1][xx];
        v.z = tile[(c4 << 2) + 2][xx];
        v.w = tile[(c4 << 2) + 3][xx];
        *(float4*)(ob + (size_t)xx * CIN + (c4 << 2)) = v;
    }
}

// ---------------------------------------------------------------------------
// Kernel 4: fused separable gather + f16 mma.sync GEMM, tap-paired staging
//   Groups: {0,2} {1} {3,5} {4} {6,8} {7} — paired taps share new_r bitwise.
//   Window bound: paired dc is mirrored, |dc| < WW/4 = 64 cols, so
//   width = (hi-lo) + 132 <= 260 < WMAX=264. No truncation possible (the
//   R14 NaN was the WMAX=252 clamp reading unstaged smem on polar rows).
//   staging: f16x2 pairs, pitch 144 B/col, [0, 38016)
//   A-frags: f16, 2 slots x 16 KB, [38016, 70784)
//   epilogue reuses [0, 65536)
// ---------------------------------------------------------------------------
#define WMAX    264
#define SPITCH  144
#define SMEM_AF 38016
#define SMEM_TOTAL 70784

__global__ __launch_bounds__(256, 2) void main_kernel(const float* __restrict__ bias,
                                                      float* __restrict__ out) {
    extern __shared__ char smem[];
    const uint32_t smem_u = (uint32_t)__cvta_generic_to_shared(smem);
    const int tid  = threadIdx.x;
    const int wid  = tid >> 5, l = tid & 31;
    const int wm   = wid & 3, wn = wid >> 2;
    const int pix0 = blockIdx.x << 7;
    const int n    = pix0 >> 15;
    const int rc0  = pix0 & (HWSZ - 1);
    const int lswz = l ^ ((l >> 2) & 7);

    // combine identity: px = tid&127, hc = tid>>7
    const int px  = tid & 127;
    const int hc  = tid >> 7;
    const int mt  = px >> 4;
    const int p7  = px & 7;
    const int hi8 = (px >> 3) & 1;

    const float* __restrict__ xb = g_xt + (size_t)n * (HWSZ * CIN);

    float acc[2][8][4];
    #pragma unroll
    for (int mi = 0; mi < 2; mi++)
        #pragma unroll
        for (int ni = 0; ni < 8; ni++)
            #pragma unroll
            for (int r = 0; r < 4; r++) acc[mi][ni][r] = 0.0f;

    const int tA[6] = {0, 1, 3, 4, 6, 7};
    const int tB[6] = {2, -1, 5, -1, 8, -1};

    #pragma unroll 1
    for (int grp = 0; grp < 6; grp++) {
        const int tapA = tA[grp], tapB = tB[grp];

        // ---- per-group row constants (iy shared bitwise across the pair) --
        float2 gA = g_grid[rc0 * NTAP + tapA];
        float iy = gA.y;
        float fy = floorf(iy);
        int   y0 = (int)fy;
        float wy1 = iy - fy, wy0 = 1.0f - wy1;
        float W0 = (y0 >= 0     && y0 < HH)     ? wy0 : 0.0f;
        float W1 = (y0 + 1 >= 0 && y0 + 1 < HH) ? wy1 : 0.0f;
        int yc0 = min(max(y0, 0), HH - 1);
        int yc1 = min(max(y0 + 1, 0), HH - 1);
        const float* __restrict__ r0 = xb + (size_t)yc0 * (WW * CIN);
        const float* __restrict__ r1 = xb + (size_t)yc1 * (WW * CIN);

        int xsA = (int)floorf(gA.x);
        int lo = xsA, hi = xsA;
        if (tapB >= 0) {
            int xsB = (int)floorf(g_grid[rc0 * NTAP + tapB].x);
            lo = min(lo, xsB);
            hi = max(hi, xsB);
        }
        int xstart = lo - 2;
        int width  = hi + 130 - xstart;        // covers [xstart, hi+129]
        width = min(width, WMAX);              // defensive only (bound: 260)

        // ---- stage: width cols x 16 chunks (4 ch), v-blend fp32 -> f16x2 --
        for (int e = tid; e < width * 16; e += 256) {
            int col = e >> 4, ck = e & 15;
            int cidx = (xstart + col) & 255;
            int off = cidx * CIN + (ck << 2);
            float4 a = *(const float4*)(r0 + off);
            float4 b = *(const float4*)(r1 + off);
            uint32_t u0 = pack_f16x2(a.x * W0 + b.x * W1, a.y * W0 + b.y * W1);
            uint32_t u1 = pack_f16x2(a.z * W0 + b.z * W1, a.w * W0 + b.w * W1);
            asm volatile("st.shared.v2.b32 [%0], {%1, %2};"
                :: "r"(smem_u + (uint32_t)(col * SPITCH + (ck << 3))),
                   "r"(u0), "r"(u1) : "memory");
        }
        __syncthreads();

        // ---- combine: packed HFMA2 horizontal blend -> f16 A-frags --------
        #pragma unroll 1
        for (int ti = 0; ti < 2; ti++) {
            int tap = ti ? tapB : tapA;
            if (tap < 0) break;
            float ix = g_grid[(rc0 + px) * NTAP + tap].x;
            float fx = floorf(ix);
            int   x0 = (int)fx;
            float wx1 = ix - fx, wx0 = 1.0f - wx1;
            float U0 = (x0 >= 0) ? wx0 : 0.0f;
            float U1 = (x0 + 1 <= WW - 1) ? wx1 : 0.0f;
            uint32_t hU0 = pack_f16x2(U0, U0);
            uint32_t hU1 = pack_f16x2(U1, U1);
            int xc0 = max(x0, 0);
            int xc1 = min(x0 + 1, WW - 1);
            // col index mod 256 is congruent with cidx; valid for width<256
            // (direct hit) and width>=256 (full coverage) alike.
            int c0i = (xc0 - xstart) & 255;
            int c1i = (xc1 - xstart) & 255;
            uint32_t p0 = smem_u + (uint32_t)(c0i * SPITCH);
            uint32_t p1 = smem_u + (uint32_t)(c1i * SPITCH);
            uint32_t fbase = smem_u + SMEM_AF + (uint32_t)(ti << 14);
            #pragma unroll
            for (int si = 0; si < 2; si++) {
                int s = (hc << 1) + si;
                uint32_t L0[4], L1[4], H0[4], H1[4];
                asm volatile("ld.shared.v4.b32 {%0,%1,%2,%3}, [%4];"
                    : "=r"(L0[0]), "=r"(L0[1]), "=r"(L0[2]), "=r"(L0[3])
                    : "r"(p0 + (s << 5)));
                asm volatile("ld.shared.v4.b32 {%0,%1,%2,%3}, [%4];"
                    : "=r"(H0[0]), "=r"(H0[1]), "=r"(H0[2]), "=r"(H0[3])
                    : "r"(p0 + (s << 5) + 16));
                asm volatile("ld.shared.v4.b32 {%0,%1,%2,%3}, [%4];"
                    : "=r"(L1[0]), "=r"(L1[1]), "=r"(L1[2]), "=r"(L1[3])
                    : "r"(p1 + (s << 5)));
                asm volatile("ld.shared.v4.b32 {%0,%1,%2,%3}, [%4];"
                    : "=r"(H1[0]), "=r"(H1[1]), "=r"(H1[2]), "=r"(H1[3])
                    : "r"(p1 + (s << 5) + 16));
                #pragma unroll
                for (int j = 0; j < 4; j++) {
                    uint32_t tl, th, lo2, hi2;
                    HMUL2(tl, L1[j], hU1);
                    HFMA2(lo2, L0[j], hU0, tl);
                    HMUL2(th, H1[j], hU1);
                    HFMA2(hi2, H0[j], hU0, th);
                    int lsw = (p7 * 4 + j) ^ p7;
                    uint32_t addr = fbase +
                        (uint32_t)((((s * 8 + mt) * 32 + lsw) << 4) + (hi8 << 3));
                    asm volatile("st.shared.v2.b32 [%0], {%1, %2};"
                        :: "r"(addr), "r"(lo2), "r"(hi2) : "memory");
                }
            }
        }
        __syncthreads();

        // ---- mma phase: 4 k16-steps per tap in the group ------------------
        #pragma unroll 1
        for (int ti = 0; ti < 2; ti++) {
            int tap = ti ? tapB : tapA;
            if (tap < 0) break;
            uint32_t fbase = smem_u + SMEM_AF + (uint32_t)(ti << 14);
            #pragma unroll
            for (int s = 0; s < 4; s++) {
                uint32_t a0[2], a1[2], a2[2], a3[2];
                #pragma unroll
                for (int mi = 0; mi < 2; mi++) {
                    uint32_t addr = fbase +
                        (uint32_t)((((s * 8 + wm * 2 + mi) * 32 + lswz)) << 4);
                    asm volatile("ld.shared.v4.b32 {%0,%1,%2,%3}, [%4];"
                        : "=r"(a0[mi]), "=r"(a2[mi]), "=r"(a1[mi]), "=r"(a3[mi])
                        : "r"(addr));
                }
                uint2 bv[8];
                #pragma unroll
                for (int ni = 0; ni < 8; ni++) {
                    int nt = wn * 8 + ni;
                    bv[ni] = g_wB[((tap * 4 + s) * 16 + nt) * 32 + l];
                }
                #pragma unroll
                for (int ni = 0; ni < 8; ni++) {
                    mma_f16(acc[0][ni], a0[0], a1[0], a2[0], a3[0], bv[ni].x, bv[ni].y);
                    mma_f16(acc[1][ni], a0[1], a1[1], a2[1], a3[1], bv[ni].x, bv[ni].y);
                }
            }
        }
        // next stage writes staging (disjoint from A-frags); the post-stage
        // sync orders everything: every thread passes its mma before staging.
    }
    __syncthreads();

    // ---- epilogue: accs -> smem [co][px] -> coalesced STG.128 --------------
    float* so = (float*)smem;
    #pragma unroll
    for (int mi = 0; mi < 2; mi++) {
        int pxr = wm * 32 + mi * 16 + (l >> 2);
        #pragma unroll
        for (int ni = 0; ni < 8; ni++) {
            int co = wn * 64 + ni * 8 + (l & 3) * 2;
            so[co * 128 + pxr]           = acc[mi][ni][0];
            so[(co + 1) * 128 + pxr]     = acc[mi][ni][1];
            so[co * 128 + pxr + 8]       = acc[mi][ni][2];
            so[(co + 1) * 128 + pxr + 8] = acc[mi][ni][3];
        }
    }
    __syncthreads();

    float* ob = out + (size_t)n * COUT * HWSZ + rc0 + (l << 2);
    #pragma unroll
    for (int it = 0; it < 16; it++) {
        int co = it * 8 + wid;
        float4 v = *(const float4*)(so + co * 128 + (l << 2));
        float bb = __ldg(&bias[co]);
        v.x += bb; v.y += bb; v.z += bb; v.w += bb;
        *(float4*)(ob + (size_t)co * HWSZ) = v;
    }
}

// ---------------------------------------------------------------------------
extern "C" void kernel_launch(void* const* d_in, const int* in_sizes, int n_in,
                              void* d_out, int out_size) {
    const float* x = (const float*)d_in[0];
    const float* w = (const float*)d_in[1];
    const float* b = (const float*)d_in[2];
    float* out = (float*)d_out;

    cudaFuncSetAttribute(main_kernel,
                         cudaFuncAttributeMaxDynamicSharedMemorySize, SMEM_TOTAL);

    grid1_kernel<<<(HH * NTAP + 127) / 128, 128>>>();
    grid2_kernel<<<(HWSZ * NTAP + 255) / 256, 256>>>();
    wb_kernel<<<(NTAP * 4 * 16 * 32 + 255) / 256, 256>>>(w);
    xt_kernel<<<NN * HH * (WW / 32), 256>>>(x);
    main_kernel<<<NN * HWSZ / 128, 256, SMEM_TOTAL>>>(b, out);
}

// round 17
// speedup vs baseline: 2.8682x; 1.0389x over previous
#include <cuda_runtime.h>
#include <cstdint>

#define HH   128
#define WW   256
#define NN   4
#define CIN  64
#define COUT 128
#define HWSZ (HH * WW)
#define NTAP 9

// Scratch (static device globals — no runtime allocation)
__device__ float    g_xt[NN * HH * WW * CIN];     // x transposed to [n][y][x][ci]
__device__ uint2    g_wB[NTAP * 4 * 16 * 32];     // weights in f16 B-fragment order
__device__ float2   g_grid[HH * WW * NTAP];       // (ix, iy) unnormalized coords
__device__ double   g_nrd[HH * NTAP];
__device__ double   g_dcd[HH * NTAP];

__device__ __forceinline__ uint32_t pack_f16x2(float lo, float hi) {
    uint32_t d;  // cvt.rn.f16x2.f32 d, a, b  ->  d.hi = a, d.lo = b
    asm("cvt.rn.f16x2.f32 %0, %1, %2;" : "=r"(d) : "f"(hi), "f"(lo));
    return d;
}
#define HMUL2(d, a, b)     asm("mul.f16x2 %0, %1, %2;" : "=r"(d) : "r"(a), "r"(b))
#define HFMA2(d, a, b, c)  asm("fma.rn.f16x2 %0, %1, %2, %3;" : "=r"(d) : "r"(a), "r"(b), "r"(c))
#define LDS32(d, a)        asm volatile("ld.shared.b32 %0, [%1];" : "=r"(d) : "r"(a))

__device__ __forceinline__ void mma_f16(float* c, uint32_t a0, uint32_t a1,
                                        uint32_t a2, uint32_t a3,
                                        uint32_t b0, uint32_t b1) {
    asm volatile(
        "mma.sync.aligned.m16n8k16.row.col.f32.f16.f16.f32 "
        "{%0,%1,%2,%3}, {%4,%5,%6,%7}, {%8,%9}, {%0,%1,%2,%3};"
        : "+f"(c[0]), "+f"(c[1]), "+f"(c[2]), "+f"(c[3])
        : "r"(a0), "r"(a1), "r"(a2), "r"(a3), "r"(b0), "r"(b1));
}

// ---------------------------------------------------------------------------
// Kernel 1a: heavy fp64 trig, only (row, tap)-dependent  (1152 points)
// ---------------------------------------------------------------------------
__global__ void grid1_kernel() {
    int idx = blockIdx.x * blockDim.x + threadIdx.x;
    if (idx >= HH * NTAP) return;
    int r = idx / NTAP, t = idx % NTAP;
    int i = t / 3, j = t % 3;
    const double PI = 3.141592653589793238462643383279502884;
    if (i == 1 && j == 1) {
        g_nrd[idx] = (double)r;
        g_dcd[idx] = 0.0;
        return;
    }
    double dphi = PI / HH, dth = 2.0 * PI / WW;
    double tt = tan(dth), pq = tan(dphi), sp = pq / cos(dth);
    double phi = -(((double)r + 0.5) / HH * PI - PI * 0.5);
    double sphi = sin(phi), cphi = cos(phi);
    double X = (j == 0) ? -tt : (j == 2) ? tt : 0.0;
    double Y;
    if (i == 0)      Y = (j == 1) ?  pq :  sp;
    else if (i == 2) Y = (j == 1) ? -pq : -sp;
    else             Y = 0.0;
    double rho = sqrt(X * X + Y * Y);
    double v   = atan(rho);
    double sv  = sin(v), cv = cos(v);
    double arg = cv * sphi + Y * sv * cphi / rho;
    arg = fmin(1.0, fmax(-1.0, arg));
    double nphi = asin(arg);
    double A    = atan((X * sv) / (rho * cphi * cv - Y * sphi * sv));
    g_nrd[idx] = (-nphi + PI * 0.5) * HH / PI - 0.5;
    g_dcd[idx] = A * WW / (2.0 * PI);
}

// ---------------------------------------------------------------------------
// Kernel 1b: expand to full per-pixel grid (fp64 adds + fp32 cast, exact)
// ---------------------------------------------------------------------------
__global__ void grid2_kernel() {
    int idx = blockIdx.x * blockDim.x + threadIdx.x;
    if (idx >= HWSZ * NTAP) return;
    int p = idx / NTAP, t = idx % NTAP;
    int r = p >> 8, c = p & 255;
    double nr = g_nrd[r * NTAP + t];
    double t2 = (double)c + g_dcd[r * NTAP + t];
    double nc = (t2 >= 0.0) ? ((t2 < 256.0) ? t2 : t2 - 256.0) : t2 + 256.0;
    float gx = (float)(nc * 2.0 / WW - 1.0);
    float gy = (float)(nr * 2.0 / HH - 1.0);
    float ix = ((gx + 1.0f) * WW - 1.0f) * 0.5f;
    float iy = ((gy + 1.0f) * HH - 1.0f) * 0.5f;
    g_grid[idx] = make_float2(ix, iy);
}

// ---------------------------------------------------------------------------
// Kernel 2: weights -> f16 B-fragment layout (m16n8k16)
// ---------------------------------------------------------------------------
__global__ void wb_kernel(const float* __restrict__ w) {
    int e = blockIdx.x * blockDim.x + threadIdx.x;
    if (e >= NTAP * 4 * 16 * 32) return;
    int l   = e & 31;
    int nt  = (e >> 5) & 15;
    int s   = (e >> 9) & 3;
    int tap = e >> 11;
    int co  = nt * 8 + (l >> 2);
    int k0  = s * 16 + 2 * (l & 3);
    float w0 = w[(co * CIN + k0) * 9 + tap];
    float w1 = w[(co * CIN + k0 + 1) * 9 + tap];
    float w2 = w[(co * CIN + k0 + 8) * 9 + tap];
    float w3 = w[(co * CIN + k0 + 9) * 9 + tap];
    uint2 v;
    v.x = pack_f16x2(w0, w1);
    v.y = pack_f16x2(w2, w3);
    g_wB[e] = v;
}

// ---------------------------------------------------------------------------
// Kernel 3: x -> channels-last transpose, float4 both directions
// ---------------------------------------------------------------------------
__global__ void xt_kernel(const float* __restrict__ x) {
    __shared__ float tile[CIN][33];
    int b  = blockIdx.x;
    int x0 = (b & 7) * 32;            // WW/32 = 8
    int ny = b >> 3;                  // n*HH + y
    int n  = ny / HH, y = ny % HH;
    const float* xb = x + (size_t)n * CIN * HWSZ + (size_t)y * WW + x0;
    #pragma unroll
    for (int it = 0; it < 2; it++) {
        int i = threadIdx.x + it * 256;     // 512 tasks: ci x f4
        int ci = i >> 3, f4 = i & 7;
        float4 v = *(const float4*)(xb + (size_t)ci * HWSZ + (f4 << 2));
        tile[ci][(f4 << 2) + 0] = v.x;
        tile[ci][(f4 << 2) + 1] = v.y;
        tile[ci][(f4 << 2) + 2] = v.z;
        tile[ci][(f4 << 2) + 3] = v.w;
    }
    __syncthreads();
    float* ob = g_xt + ((size_t)ny * WW + x0) * CIN;
    #pragma unroll
    for (int it = 0; it < 2; it++) {
        int i = threadIdx.x + it * 256;     // 512 tasks: xx x c4
        int xx = i >> 4, c4 = i & 15;
        float4 v;
        v.x = tile[(c4 << 2) + 0][xx];
        v.y = tile[(c4 << 2) + 1][xx];
        v.z = tile[(c4 << 2) + 2][xx];
        v.w = tile[(c4 << 2) + 3][xx];
        *(float4*)(ob + (size_t)xx * CIN + (c4 << 2)) = v;
    }
}

// ---------------------------------------------------------------------------
// Kernel 4: pipelined separable gather + register-direct f16 mma.sync GEMM
//   Per group: stage (v-blend -> f16 staging, double-buffered) + ixinfo
//   (per-px horizontal offsets + f16x2 weights).  The mma loop computes A
//   fragments DIRECTLY in registers from staging (2x LDS.32 + HMUL2/HFMA2
//   per fragment) — no A-frag smem, no combine phase.  Group g+1's stage is
//   issued before group g's mma so its LDG latency hides under tensor work.
//   One __syncthreads per group.
//   smem: buf0 [0,38016)  buf1 [38016,76032)  ixinfo 2x4KB [76032,84224)
// ---------------------------------------------------------------------------
#define WMAX    264
#define SPITCH  144
#define BUFSZ   38016
#define IXOFF   76032
#define SMEM_TOTAL 84224

struct GroupCtx {
    float W0, W1;
    int yc0, yc1, xstart, width;
};

__global__ __launch_bounds__(256, 2) void main_kernel(const float* __restrict__ bias,
                                                      float* __restrict__ out) {
    extern __shared__ char smem[];
    const uint32_t smem_u = (uint32_t)__cvta_generic_to_shared(smem);
    const int tid  = threadIdx.x;
    const int wid  = tid >> 5, l = tid & 31;
    const int wm   = wid & 3, wn = wid >> 2;
    const int pix0 = blockIdx.x << 7;
    const int n    = pix0 >> 15;
    const int rc0  = pix0 & (HWSZ - 1);

    const float* __restrict__ xb = g_xt + (size_t)n * (HWSZ * CIN);

    const int tA[6] = {0, 1, 3, 4, 6, 7};
    const int tB[6] = {2, -1, 5, -1, 6 + 2, -1};

    float acc[2][8][4];
    #pragma unroll
    for (int mi = 0; mi < 2; mi++)
        #pragma unroll
        for (int ni = 0; ni < 8; ni++)
            #pragma unroll
            for (int r = 0; r < 4; r++) acc[mi][ni][r] = 0.0f;

    // ---- stage one group: v-blend rows into f16 staging + build ixinfo ----
    auto stage_group = [&](int grp) {
        const int tapA = tA[grp], tapB = tB[grp];
        const uint32_t bufb = smem_u + (uint32_t)((grp & 1) * BUFSZ);
        const uint32_t ixb  = smem_u + IXOFF + (uint32_t)((grp & 1) * 4096);

        float2 gA = g_grid[rc0 * NTAP + tapA];
        float iy = gA.y;
        float fy = floorf(iy);
        int   y0 = (int)fy;
        float wy1 = iy - fy, wy0 = 1.0f - wy1;
        float W0 = (y0 >= 0     && y0 < HH)     ? wy0 : 0.0f;
        float W1 = (y0 + 1 >= 0 && y0 + 1 < HH) ? wy1 : 0.0f;
        int yc0 = min(max(y0, 0), HH - 1);
        int yc1 = min(max(y0 + 1, 0), HH - 1);
        const float* __restrict__ r0 = xb + (size_t)yc0 * (WW * CIN);
        const float* __restrict__ r1 = xb + (size_t)yc1 * (WW * CIN);

        int xsA = (int)floorf(gA.x);
        int lo = xsA, hi = xsA;
        if (tapB >= 0) {
            int xsB = (int)floorf(g_grid[rc0 * NTAP + tapB].x);
            lo = min(lo, xsB);
            hi = max(hi, xsB);
        }
        int xstart = lo - 2;
        int width  = min(hi + 130 - xstart, WMAX);   // bound: 260

        // ixinfo: per (tap, px): staged byte-offsets + f16x2 blend weights
        {
            int ti = tid >> 7, px = tid & 127;
            int tap = ti ? tapB : tapA;
            if (tap >= 0) {
                float ix = g_grid[(rc0 + px) * NTAP + tap].x;
                float fx = floorf(ix);
                int   x0 = (int)fx;
                float wx1 = ix - fx, wx0 = 1.0f - wx1;
                float U0 = (x0 >= 0) ? wx0 : 0.0f;
                float U1 = (x0 + 1 <= WW - 1) ? wx1 : 0.0f;
                int xc0 = max(x0, 0);
                int xc1 = min(x0 + 1, WW - 1);
                uint32_t o0 = (uint32_t)(((xc0 - xstart) & 255) * SPITCH);
                uint32_t o1 = (uint32_t)(((xc1 - xstart) & 255) * SPITCH);
                uint32_t hx = o0 | (o1 << 16);
                uint32_t hu0 = pack_f16x2(U0, U0);
                uint32_t hu1 = pack_f16x2(U1, U1);
                asm volatile("st.shared.v4.b32 [%0], {%1,%2,%3,%4};"
                    :: "r"(ixb + (uint32_t)((ti * 128 + px) << 4)),
                       "r"(hx), "r"(hu0), "r"(hu1), "r"(0u) : "memory");
            }
        }

        // staged data: width cols x 16 chunks (4 ch), v-blend fp32 -> f16x2
        for (int e = tid; e < width * 16; e += 256) {
            int col = e >> 4, ck = e & 15;
            int cidx = (xstart + col) & 255;
            int off = cidx * CIN + (ck << 2);
            float4 a = *(const float4*)(r0 + off);
            float4 b = *(const float4*)(r1 + off);
            uint32_t u0 = pack_f16x2(a.x * W0 + b.x * W1, a.y * W0 + b.y * W1);
            uint32_t u1 = pack_f16x2(a.z * W0 + b.z * W1, a.w * W0 + b.w * W1);
            asm volatile("st.shared.v2.b32 [%0], {%1, %2};"
                :: "r"(bufb + (uint32_t)(col * SPITCH + (ck << 3))),
                   "r"(u0), "r"(u1) : "memory");
        }
    };

    stage_group(0);

    #pragma unroll 1
    for (int grp = 0; grp < 6; grp++) {
        __syncthreads();                     // stage(grp) visible; buf reuse safe
        if (grp < 5) stage_group(grp + 1);   // overlap next stage with this mma

        const uint32_t bufb = smem_u + (uint32_t)((grp & 1) * BUFSZ);
        const uint32_t ixb  = smem_u + IXOFF + (uint32_t)((grp & 1) * 4096);
        const int tapA = tA[grp], tapB = tB[grp];

        #pragma unroll 1
        for (int ti = 0; ti < 2; ti++) {
            int tap = ti ? tapB : tapA;
            if (tap < 0) break;
            // per-thread pixel infos: px = wm*32 + (l>>2) + {0,8,16,24}
            uint4 info[4];
            uint32_t O0[4], O1[4];
            #pragma unroll
            for (int m = 0; m < 4; m++) {
                uint32_t a = ixb + (uint32_t)(((ti * 128) + wm * 32 + (l >> 2) + m * 8) << 4);
                asm volatile("ld.shared.v4.b32 {%0,%1,%2,%3}, [%4];"
                    : "=r"(info[m].x), "=r"(info[m].y), "=r"(info[m].z), "=r"(info[m].w)
                    : "r"(a));
                O0[m] = bufb + (info[m].x & 0xFFFFu);
                O1[m] = bufb + (info[m].x >> 16);
            }
            #pragma unroll
            for (int s = 0; s < 4; s++) {
                uint2 bv[8];
                #pragma unroll
                for (int ni = 0; ni < 8; ni++) {
                    int nt = wn * 8 + ni;
                    bv[ni] = g_wB[((tap * 4 + s) * 16 + nt) * 32 + l];
                }
                uint32_t cpb = (uint32_t)(((s * 8) + (l & 3)) << 2);
                uint32_t A0[2], A1[2], A2[2], A3[2];
                #pragma unroll
                for (int mi = 0; mi < 2; mi++) {
                    int ma = mi * 2, mb = mi * 2 + 1;
                    uint32_t v0, v1, t;
                    // a0: px_a, ch pair lo
                    LDS32(v0, O0[ma] + cpb); LDS32(v1, O1[ma] + cpb);
                    HMUL2(t, v1, info[ma].z); HFMA2(A0[mi], v0, info[ma].y, t);
                    // a2: px_a, ch pair hi (+4 pairs = +16B)
                    LDS32(v0, O0[ma] + cpb + 16); LDS32(v1, O1[ma] + cpb + 16);
                    HMUL2(t, v1, info[ma].z); HFMA2(A2[mi], v0, info[ma].y, t);
                    // a1: px_b, ch pair lo
                    LDS32(v0, O0[mb] + cpb); LDS32(v1, O1[mb] + cpb);
                    HMUL2(t, v1, info[mb].z); HFMA2(A1[mi], v0, info[mb].y, t);
                    // a3: px_b, ch pair hi
                    LDS32(v0, O0[mb] + cpb + 16); LDS32(v1, O1[mb] + cpb + 16);
                    HMUL2(t, v1, info[mb].z); HFMA2(A3[mi], v0, info[mb].y, t);
                }
                #pragma unroll
                for (int ni = 0; ni < 8; ni++) {
                    mma_f16(acc[0][ni], A0[0], A1[0], A2[0], A3[0], bv[ni].x, bv[ni].y);
                    mma_f16(acc[1][ni], A0[1], A1[1], A2[1], A3[1], bv[ni].x, bv[ni].y);
                }
            }
        }
    }
    __syncthreads();

    // ---- epilogue: accs -> smem [co][px] -> coalesced STG.128 --------------
    float* so = (float*)smem;
    #pragma unroll
    for (int mi = 0; mi < 2; mi++) {
        int pxr = wm * 32 + mi * 16 + (l >> 2);
        #pragma unroll
        for (int ni = 0; ni < 8; ni++) {
            int co = wn * 64 + ni * 8 + (l & 3) * 2;
            so[co * 128 + pxr]           = acc[mi][ni][0];
            so[(co + 1) * 128 + pxr]     = acc[mi][ni][1];
            so[co * 128 + pxr + 8]       = acc[mi][ni][2];
            so[(co + 1) * 128 + pxr + 8] = acc[mi][ni][3];
        }
    }
    __syncthreads();

    float* ob = out + (size_t)n * COUT * HWSZ + rc0 + (l << 2);
    #pragma unroll
    for (int it = 0; it < 16; it++) {
        int co = it * 8 + wid;
        float4 v = *(const float4*)(so + co * 128 + (l << 2));
        float bb = __ldg(&bias[co]);
        v.x += bb; v.y += bb; v.z += bb; v.w += bb;
        *(float4*)(ob + (size_t)co * HWSZ) = v;
    }
}

// ---------------------------------------------------------------------------
extern "C" void kernel_launch(void* const* d_in, const int* in_sizes, int n_in,
                              void* d_out, int out_size) {
    const float* x = (const float*)d_in[0];
    const float* w = (const float*)d_in[1];
    const float* b = (const float*)d_in[2];
    float* out = (float*)d_out;

    cudaFuncSetAttribute(main_kernel,
                         cudaFuncAttributeMaxDynamicSharedMemorySize, SMEM_TOTAL);

    grid1_kernel<<<(HH * NTAP + 127) / 128, 128>>>();
    grid2_kernel<<<(HWSZ * NTAP + 255) / 256, 256>>>();
    wb_kernel<<<(NTAP * 4 * 16 * 32 + 255) / 256, 256>>>(w);
    xt_kernel<<<NN * HH * (WW / 32), 256>>>(x);
    main_kernel<<<NN * HWSZ / 128, 256, SMEM_TOTAL>>>(b, out);
}